// round 1
// baseline (speedup 1.0000x reference)
#include <cuda_runtime.h>
#include <cuda_bf16.h>
#include <math.h>

// Problem constants
#define BATCH 4
#define CIN   512     // C
#define CK    256
#define CV    256
#define QKV   768     // CK + CK + CV
#define NPIX  4096    // H*W
#define EPSBN 1e-5f

// ---------------- scratch (device globals; no allocation allowed) -------------
static __device__ float g_wT[CIN * QKV];            // [c][o] transposed qkv weights
static __device__ float g_bias[QKV];                // concat bq,bk,bv
static __device__ float g_wWT[CV * CIN];            // [cv][co] transposed wW
static __device__ float g_Z[(size_t)BATCH * QKV * NPIX];      // qkv raw / post-BN (50MB)
static __device__ float g_S[(size_t)BATCH * NPIX * NPIX];     // attention scores (268MB)
static __device__ float g_ctx[(size_t)BATCH * CV * NPIX];     // context (17MB)
static __device__ float g_bnA[2 * CK];              // per-channel scale (q then k)
static __device__ float g_bnB[2 * CK];              // per-channel shift

// ---------------- prep: transpose weights, concat bias ------------------------
__global__ void prep_kernel(const float* __restrict__ wq, const float* __restrict__ bq,
                            const float* __restrict__ wk, const float* __restrict__ bk,
                            const float* __restrict__ wv, const float* __restrict__ bv,
                            const float* __restrict__ wW) {
    int idx = blockIdx.x * blockDim.x + threadIdx.x;
    if (idx < QKV * CIN) {
        int o = idx % QKV;
        int c = idx / QKV;
        const float* w; int oo;
        if (o < CK)          { w = wq; oo = o; }
        else if (o < 2 * CK) { w = wk; oo = o - CK; }
        else                 { w = wv; oo = o - 2 * CK; }
        g_wT[idx] = w[oo * CIN + c];
    }
    if (idx < CV * CIN) {
        int co = idx % CIN;
        int cv = idx / CIN;
        g_wWT[idx] = wW[co * CV + cv];
    }
    if (idx < QKV) {
        g_bias[idx] = (idx < CK) ? bq[idx] : (idx < 2 * CK) ? bk[idx - CK] : bv[idx - 2 * CK];
    }
}

// ---------------- GEMM TN: C[i,j] = alpha * sum_k A[k*lda+i]*B[k*ldb+j] -------
// A: K x M (row-major), B: K x N (row-major), C: M x N (row-major)
#define BM 128
#define BN 128
#define BKT 8
#define TM 8
#define TNN 8

__global__ void __launch_bounds__(256)
gemm_tn(const float* __restrict__ A, const float* __restrict__ B, float* __restrict__ C,
        int M, int N, int K, int lda, int ldb, int ldc,
        long sA, long sB, long sC,
        const float* __restrict__ bias,
        const float* __restrict__ resid, long sR,
        float alpha)
{
    __shared__ float As[BKT][BM];
    __shared__ float Bs[BKT][BN];
    int bz = blockIdx.z;
    A += (long)bz * sA;
    B += (long)bz * sB;
    C += (long)bz * sC;
    if (resid) resid += (long)bz * sR;

    int i0 = blockIdx.y * BM;
    int j0 = blockIdx.x * BN;
    int tid = threadIdx.x;
    int tx = tid % 16, ty = tid / 16;

    float acc[TM][TNN];
    #pragma unroll
    for (int m = 0; m < TM; m++)
        #pragma unroll
        for (int n = 0; n < TNN; n++) acc[m][n] = 0.f;

    for (int k0 = 0; k0 < K; k0 += BKT) {
        #pragma unroll
        for (int r = 0; r < 4; r++) {
            int kk = r * 2 + tid / 128;
            int ii = tid % 128;
            As[kk][ii] = A[(long)(k0 + kk) * lda + i0 + ii];
            Bs[kk][ii] = B[(long)(k0 + kk) * ldb + j0 + ii];
        }
        __syncthreads();
        #pragma unroll
        for (int kk = 0; kk < BKT; kk++) {
            float a[TM], b[TNN];
            #pragma unroll
            for (int m = 0; m < TM; m++) a[m] = As[kk][ty * TM + m];
            #pragma unroll
            for (int n = 0; n < TNN; n++) b[n] = Bs[kk][tx * TNN + n];
            #pragma unroll
            for (int m = 0; m < TM; m++)
                #pragma unroll
                for (int n = 0; n < TNN; n++)
                    acc[m][n] += a[m] * b[n];
        }
        __syncthreads();
    }

    #pragma unroll
    for (int m = 0; m < TM; m++) {
        int i = i0 + ty * TM + m;
        float bi = bias ? bias[i] : 0.f;
        #pragma unroll
        for (int n = 0; n < TNN; n++) {
            int j = j0 + tx * TNN + n;
            float v = acc[m][n] * alpha + bi;
            if (resid) v += resid[(long)i * ldc + j];
            C[(long)i * ldc + j] = v;
        }
    }
}

// ---------------- GEMM NT: C[i,j] = sum_k A[i*lda+k]*B[j*ldb+k] ---------------
// A: M x K (row-major), B: N x K (row-major), C: M x N (row-major)
__global__ void __launch_bounds__(256)
gemm_nt(const float* __restrict__ A, const float* __restrict__ B, float* __restrict__ C,
        int M, int N, int K, int lda, int ldb, int ldc,
        long sA, long sB, long sC)
{
    __shared__ float As[BKT][BM + 4];
    __shared__ float Bs[BKT][BN + 4];
    int bz = blockIdx.z;
    A += (long)bz * sA;
    B += (long)bz * sB;
    C += (long)bz * sC;

    int i0 = blockIdx.y * BM;
    int j0 = blockIdx.x * BN;
    int tid = threadIdx.x;
    int tx = tid % 16, ty = tid / 16;

    float acc[TM][TNN];
    #pragma unroll
    for (int m = 0; m < TM; m++)
        #pragma unroll
        for (int n = 0; n < TNN; n++) acc[m][n] = 0.f;

    for (int k0 = 0; k0 < K; k0 += BKT) {
        #pragma unroll
        for (int r = 0; r < 4; r++) {
            int t = r * 256 + tid;
            int ii = t / BKT;
            int kk = t % BKT;
            As[kk][ii] = A[(long)(i0 + ii) * lda + k0 + kk];
            Bs[kk][ii] = B[(long)(j0 + ii) * ldb + k0 + kk];
        }
        __syncthreads();
        #pragma unroll
        for (int kk = 0; kk < BKT; kk++) {
            float a[TM], b[TNN];
            #pragma unroll
            for (int m = 0; m < TM; m++) a[m] = As[kk][ty * TM + m];
            #pragma unroll
            for (int n = 0; n < TNN; n++) b[n] = Bs[kk][tx * TNN + n];
            #pragma unroll
            for (int m = 0; m < TM; m++)
                #pragma unroll
                for (int n = 0; n < TNN; n++)
                    acc[m][n] += a[m] * b[n];
        }
        __syncthreads();
    }

    #pragma unroll
    for (int m = 0; m < TM; m++) {
        int i = i0 + ty * TM + m;
        #pragma unroll
        for (int n = 0; n < TNN; n++) {
            int j = j0 + tx * TNN + n;
            C[(long)i * ldc + j] = acc[m][n];
        }
    }
}

// ---------------- BN stats over (B, N) for q and k channels --------------------
__global__ void bn_stats(const float* __restrict__ gq, const float* __restrict__ betaq,
                         const float* __restrict__ gk, const float* __restrict__ betak)
{
    int o = blockIdx.x;   // 0..511 : row o of each batch's Z (q rows 0..255, k rows 256..511)
    int t = threadIdx.x;
    __shared__ float rs[256], rq[256];
    float s = 0.f, sq = 0.f;
    for (int b = 0; b < BATCH; b++) {
        const float* p = g_Z + ((long)b * QKV + o) * NPIX;
        for (int i = t; i < NPIX; i += 256) {
            float v = p[i];
            s += v;
            sq += v * v;
        }
    }
    rs[t] = s; rq[t] = sq;
    __syncthreads();
    for (int st = 128; st > 0; st >>= 1) {
        if (t < st) { rs[t] += rs[t + st]; rq[t] += rq[t + st]; }
        __syncthreads();
    }
    if (t == 0) {
        float cnt = (float)(BATCH * NPIX);
        float mean = rs[0] / cnt;
        float var = rq[0] / cnt - mean * mean;
        float inv = rsqrtf(var + EPSBN);
        float gamma = (o < CK) ? gq[o] : gk[o - CK];
        float beta  = (o < CK) ? betaq[o] : betak[o - CK];
        g_bnA[o] = gamma * inv;
        g_bnB[o] = beta - mean * gamma * inv;
    }
}

// ---------------- BN apply + ReLU in place on q,k rows of Z -------------------
__global__ void bn_apply(void)
{
    long idx = (long)blockIdx.x * blockDim.x + threadIdx.x;
    // total: BATCH * 512 * NPIX
    int n = (int)(idx % NPIX);
    int o = (int)((idx / NPIX) % (2 * CK));
    int b = (int)(idx / ((long)NPIX * 2 * CK));
    long off = ((long)b * QKV + o) * NPIX + n;
    float z = g_Z[off] * g_bnA[o] + g_bnB[o];
    g_Z[off] = z > 0.f ? z : 0.f;
}

// ---------------- row softmax over last dim of S ------------------------------
__global__ void __launch_bounds__(256) softmax_rows(void)
{
    long row = blockIdx.x;                   // b*NPIX + n
    float* p = g_S + row * NPIX;
    __shared__ float buf[NPIX];
    __shared__ float red[256];
    int t = threadIdx.x;

    float mx = -1e30f;
    for (int i = t; i < NPIX; i += 256) {
        float v = p[i];
        buf[i] = v;
        mx = fmaxf(mx, v);
    }
    red[t] = mx;
    __syncthreads();
    for (int s = 128; s > 0; s >>= 1) {
        if (t < s) red[t] = fmaxf(red[t], red[t + s]);
        __syncthreads();
    }
    mx = red[0];
    __syncthreads();

    float sum = 0.f;
    for (int i = t; i < NPIX; i += 256) {
        float e = __expf(buf[i] - mx);
        buf[i] = e;
        sum += e;
    }
    red[t] = sum;
    __syncthreads();
    for (int s = 128; s > 0; s >>= 1) {
        if (t < s) red[t] += red[t + s];
        __syncthreads();
    }
    float inv = 1.f / red[0];
    for (int i = t; i < NPIX; i += 256) p[i] = buf[i] * inv;
}

// ---------------- launch ------------------------------------------------------
extern "C" void kernel_launch(void* const* d_in, const int* in_sizes, int n_in,
                              void* d_out, int out_size)
{
    const float* x     = (const float*)d_in[0];
    const float* wq    = (const float*)d_in[1];
    const float* bq    = (const float*)d_in[2];
    const float* gq    = (const float*)d_in[3];
    const float* betaq = (const float*)d_in[4];
    const float* wk    = (const float*)d_in[5];
    const float* bk    = (const float*)d_in[6];
    const float* gk    = (const float*)d_in[7];
    const float* betak = (const float*)d_in[8];
    const float* wv    = (const float*)d_in[9];
    const float* bv    = (const float*)d_in[10];
    const float* wW    = (const float*)d_in[11];
    const float* bW    = (const float*)d_in[12];
    float* out = (float*)d_out;

    float *pwT, *pbias, *pwWT, *pZ, *pS, *pctx;
    cudaGetSymbolAddress((void**)&pwT, g_wT);
    cudaGetSymbolAddress((void**)&pbias, g_bias);
    cudaGetSymbolAddress((void**)&pwWT, g_wWT);
    cudaGetSymbolAddress((void**)&pZ, g_Z);
    cudaGetSymbolAddress((void**)&pS, g_S);
    cudaGetSymbolAddress((void**)&pctx, g_ctx);

    // 1. transpose weights / concat bias
    prep_kernel<<<(QKV * CIN + 255) / 256, 256>>>(wq, bq, wk, bk, wv, bv, wW);

    // 2. qkv projection: Z[b, o, n] = sum_c wT[c, o] * x[b, c, n] + bias[o]
    {
        dim3 grid(NPIX / BN, QKV / BM, BATCH);
        gemm_tn<<<grid, 256>>>(pwT, x, pZ,
                               QKV, NPIX, CIN, QKV, NPIX, NPIX,
                               0L, (long)CIN * NPIX, (long)QKV * NPIX,
                               pbias, nullptr, 0L, 1.0f);
    }

    // 3. BN stats + 4. BN apply + ReLU (q and k rows)
    bn_stats<<<2 * CK, 256>>>(gq, betaq, gk, betak);
    bn_apply<<<(int)(((long)BATCH * 2 * CK * NPIX) / 256), 256>>>();

    // 5. scores: S[b, n, m] = (1/16) * sum_c k[b, c, n] * q[b, c, m]
    {
        dim3 grid(NPIX / BN, NPIX / BM, BATCH);
        gemm_tn<<<grid, 256>>>(pZ + (long)CK * NPIX, pZ, pS,
                               NPIX, NPIX, CK, NPIX, NPIX, NPIX,
                               (long)QKV * NPIX, (long)QKV * NPIX, (long)NPIX * NPIX,
                               nullptr, nullptr, 0L, 0.0625f);
    }

    // 6. softmax over m
    softmax_rows<<<BATCH * NPIX, 256>>>();

    // 7. ctx[b, c, n] = sum_m v[b, c, m] * P[b, n, m]
    {
        dim3 grid(NPIX / BN, CV / BM, BATCH);
        gemm_nt<<<grid, 256>>>(pZ + (long)2 * CK * NPIX, pS, pctx,
                               CV, NPIX, NPIX, NPIX, NPIX, NPIX,
                               (long)QKV * NPIX, (long)NPIX * NPIX, (long)CV * NPIX);
    }

    // 8. out[b, co, n] = sum_cv wWT[cv, co] * ctx[b, cv, n] + bW[co] + x[b, co, n]
    {
        dim3 grid(NPIX / BN, CIN / BM, BATCH);
        gemm_tn<<<grid, 256>>>(pwWT, pctx, out,
                               CIN, NPIX, CV, CIN, NPIX, NPIX,
                               0L, (long)CV * NPIX, (long)CIN * NPIX,
                               bW, x, (long)CIN * NPIX, 1.0f);
    }
}